// round 11
// baseline (speedup 1.0000x reference)
#include <cuda_runtime.h>
#include <cuda_bf16.h>
#include <cstdint>

// TopKRouter: mma.sync bf16 2-way split (hh+hm+mh), m16n64 warp tile,
// TM=32 (2 m-stripes x 2 K-halves), grid 512.
// A streamed via warp-private cp.async ring (depth 4, no block barriers);
// B pre-packed per-lane fragments (k-permuted), single-buffer LDG (L1-hot).
// out (f32): [0,32768) topk_idx ; [32768,65536) topk_probs ; [65536,..) probs.

#define D_DIM   2048
#define E_DIM   64
#define BSZ     16384
#define TM      32
#define NK16    (D_DIM / 16)    // 128 k16-steps total
#define THREADS 128
#define EPS     1e-9f
#define LS_STRIDE 65
#define DEPTH   4

// B fragments: [i(128 k16-steps)][s(2)][g(4)][lane(32)] uint4
__device__ uint4 g_bfrag[NK16 * 2 * 4 * 32];

__device__ __forceinline__ uint32_t pack2(__nv_bfloat16 a, __nv_bfloat16 b) {
    __nv_bfloat162 t; t.x = a; t.y = b;
    return *(uint32_t*)&t;
}
__device__ __forceinline__ __nv_bfloat16 split_sel(float v, int s) {
    __nv_bfloat16 bh = __float2bfloat16_rn(v);
    if (s == 0) return bh;
    return __float2bfloat16_rn(v - __bfloat162float(bh));
}

// k-PERMUTED layout: slots (2t,2t+1)->k=4t+0,1 ; slots (2t+8,2t+9)->k=4t+2,3
__global__ void prep_w_kernel(const float* __restrict__ w) {
    int t = blockIdx.x * blockDim.x + threadIdx.x;
    if (t >= NK16 * 2 * 4 * 32) return;
    int lane = t & 31;
    int rest = t >> 5;
    int g  = rest & 3;  rest >>= 2;
    int s  = rest & 1;  rest >>= 1;
    int i  = rest;                      // k16 step 0..127
    uint32_t r[4];
    #pragma unroll
    for (int tt = 0; tt < 2; tt++) {
        int n = (g * 2 + tt) * 8 + (lane >> 2);
        #pragma unroll
        for (int bb = 0; bb < 2; bb++) {
            int k0 = i * 16 + 4 * (lane & 3) + bb * 2;   // permuted
            float v0 = w[(size_t)n * D_DIM + k0];
            float v1 = w[(size_t)n * D_DIM + k0 + 1];
            r[tt * 2 + bb] = pack2(split_sel(v0, s), split_sel(v1, s));
        }
    }
    g_bfrag[t] = make_uint4(r[0], r[1], r[2], r[3]);
}

__device__ __forceinline__ void mma16816(float* d, const uint32_t* a,
                                         uint32_t b0, uint32_t b1) {
    asm volatile(
        "mma.sync.aligned.m16n8k16.row.col.f32.bf16.bf16.f32 "
        "{%0,%1,%2,%3}, {%4,%5,%6,%7}, {%8,%9}, {%0,%1,%2,%3};"
        : "+f"(d[0]), "+f"(d[1]), "+f"(d[2]), "+f"(d[3])
        : "r"(a[0]), "r"(a[1]), "r"(a[2]), "r"(a[3]), "r"(b0), "r"(b1));
}

__device__ __forceinline__ void cvt_split(float vx, float vy,
                                          uint32_t& h, uint32_t& m) {
    asm("cvt.rn.bf16x2.f32 %0, %1, %2;" : "=r"(h) : "f"(vy), "f"(vx));
    float h0 = __uint_as_float(h << 16);
    float h1 = __uint_as_float(h & 0xffff0000u);
    float r0 = vx - h0;
    float r1 = vy - h1;
    asm("cvt.rn.bf16x2.f32 %0, %1, %2;" : "=r"(m) : "f"(r1), "f"(r0));
}

__device__ __forceinline__ uint32_t smem_u32(const void* p) {
    uint32_t a;
    asm("{ .reg .u64 t; cvta.to.shared.u64 t, %1; cvt.u32.u64 %0, t; }" : "=r"(a) : "l"(p));
    return a;
}
__device__ __forceinline__ void cp16(uint32_t dst, const void* src) {
    asm volatile("cp.async.cg.shared.global [%0], [%1], 16;"
                 :: "r"(dst), "l"(src) : "memory");
}
#define CP_COMMIT() asm volatile("cp.async.commit_group;" ::: "memory")
#define CP_WAIT3()  asm volatile("cp.async.wait_group 3;" ::: "memory")

__global__ __launch_bounds__(THREADS, 5)
void topk_router_mma(const float* __restrict__ x, float* __restrict__ out)
{
    __shared__ float ls[TM][LS_STRIDE];
    __shared__ uint4 ring[4][DEPTH][64];   // [warp][stage][512B xr0 | 512B xr1]

    const int tid  = threadIdx.x;
    const int wid  = tid >> 5;
    const int lane = tid & 31;
    const int ms   = wid & 1;      // m-stripe (16 rows)
    const int kg   = wid >> 1;     // K half
    const int m0w  = blockIdx.x * TM + ms * 16;
    const int r    = lane >> 2;
    const int t4   = lane & 3;

    const float* xr0 = x + (size_t)(m0w + r)     * D_DIM + t4 * 4;
    const float* xr1 = x + (size_t)(m0w + r + 8) * D_DIM + t4 * 4;

    const uint32_t rb   = smem_u32(&ring[wid][0][0]);
    const uint32_t dst0 = rb + lane * 16;         // xr0 slot
    const uint32_t dst1 = rb + 512 + lane * 16;   // xr1 slot

    float acc[8][4];
    #pragma unroll
    for (int j = 0; j < 8; j++)
        #pragma unroll
        for (int q = 0; q < 4; q++) acc[j][q] = 0.0f;

    const int HALF = NK16 / 2;         // 64 k16-steps per warp
    const int i0 = kg * HALF;

    // prologue: stages 0..2 in flight
    #pragma unroll
    for (int s = 0; s < DEPTH - 1; s++) {
        const int ii = i0 + s;
        cp16(dst0 + s * 1024, &xr0[ii * 16]);
        cp16(dst1 + s * 1024, &xr1[ii * 16]);
        CP_COMMIT();
    }

    #pragma unroll 4
    for (int i = 0; i < HALF; i++) {
        const int st = i & (DEPTH - 1);

        // issue stage i+3 (or an empty group at the tail to keep counts aligned)
        if (i + DEPTH - 1 < HALF) {
            const int ii = i0 + i + DEPTH - 1;
            const int sn = (i + DEPTH - 1) & (DEPTH - 1);
            cp16(dst0 + sn * 1024, &xr0[ii * 16]);
            cp16(dst1 + sn * 1024, &xr1[ii * 16]);
        }
        CP_COMMIT();
        CP_WAIT3();   // stage i complete

        // B fragments for step i0+i (L1/L2-hot): 8 x LDG.128
        const uint4* pb = g_bfrag + (size_t)(i0 + i) * 256 + lane;
        uint4 qh[4], qm[4];
        #pragma unroll
        for (int g = 0; g < 4; g++) {
            qh[g] = pb[g * 32];
            qm[g] = pb[128 + g * 32];
        }

        // A from ring
        uint4 a0 = *(const uint4*)((const char*)ring + (dst0 - rb) + st * 1024
                                   + (rb - smem_u32(ring)) * 0);
        // (use direct smem pointer arithmetic instead)
        a0 = ring[wid][st][lane];
        uint4 a1 = ring[wid][st][32 + lane];

        uint32_t ah[4], am[4];
        cvt_split(__uint_as_float(a0.x), __uint_as_float(a0.y), ah[0], am[0]);
        cvt_split(__uint_as_float(a1.x), __uint_as_float(a1.y), ah[1], am[1]);
        cvt_split(__uint_as_float(a0.z), __uint_as_float(a0.w), ah[2], am[2]);
        cvt_split(__uint_as_float(a1.z), __uint_as_float(a1.w), ah[3], am[3]);

        #pragma unroll
        for (int g = 0; g < 4; g++) {
            mma16816(acc[2*g],   ah, qh[g].x, qh[g].y);   // hh
            mma16816(acc[2*g+1], ah, qh[g].z, qh[g].w);
            mma16816(acc[2*g],   ah, qm[g].x, qm[g].y);   // hm
            mma16816(acc[2*g+1], ah, qm[g].z, qm[g].w);
            mma16816(acc[2*g],   am, qh[g].x, qh[g].y);   // mh
            mma16816(acc[2*g+1], am, qh[g].z, qh[g].w);
        }
    }

    // ---- combine K halves + stash logits ----
    const int row  = ms * 16 + r;
    const int colb = 2 * t4;

    if (kg == 1) {
        #pragma unroll
        for (int j = 0; j < 8; j++) {
            ls[row][colb + j * 8]         = acc[j][0];
            ls[row][colb + j * 8 + 1]     = acc[j][1];
            ls[row + 8][colb + j * 8]     = acc[j][2];
            ls[row + 8][colb + j * 8 + 1] = acc[j][3];
        }
    }
    __syncthreads();
    if (kg == 0) {
        #pragma unroll
        for (int j = 0; j < 8; j++) {
            ls[row][colb + j * 8]         += acc[j][0];
            ls[row][colb + j * 8 + 1]     += acc[j][1];
            ls[row + 8][colb + j * 8]     += acc[j][2];
            ls[row + 8][colb + j * 8 + 1] += acc[j][3];
        }
    }
    __syncthreads();

    // ---- softmax + top-2, one token per thread ----
    if (tid < TM) {
        const int token = blockIdx.x * TM + tid;
        float* row_p = &ls[tid][0];

        float mx = -1e30f;
        #pragma unroll
        for (int e = 0; e < E_DIM; e++) mx = fmaxf(mx, row_p[e]);

        float sum = 0.0f;
        #pragma unroll
        for (int e = 0; e < E_DIM; e++) {
            float ev = expf(row_p[e] - mx);
            row_p[e] = ev;
            sum += ev;
        }
        float inv = 1.0f / sum;

        float* __restrict__ out_p = out + 4 * BSZ + (size_t)token * E_DIM;
        float p1 = -1.0f, p2 = -1.0f;
        int   i1 = 0,     i2 = 0;
        #pragma unroll
        for (int e = 0; e < E_DIM; e += 4) {
            float4 pv = make_float4(row_p[e] * inv, row_p[e+1] * inv,
                                    row_p[e+2] * inv, row_p[e+3] * inv);
            *(float4*)&out_p[e] = pv;
            float pe[4] = {pv.x, pv.y, pv.z, pv.w};
            #pragma unroll
            for (int j = 0; j < 4; j++) {
                if (pe[j] > p1)      { p2 = p1; i2 = i1; p1 = pe[j]; i1 = e + j; }
                else if (pe[j] > p2) { p2 = pe[j]; i2 = e + j; }
            }
        }

        float denom = p1 + p2 + EPS;
        out[token * 2 + 0] = (float)i1;
        out[token * 2 + 1] = (float)i2;
        out[2 * BSZ + token * 2 + 0] = p1 / denom;
        out[2 * BSZ + token * 2 + 1] = p2 / denom;
    }
}

extern "C" void kernel_launch(void* const* d_in, const int* in_sizes, int n_in,
                              void* d_out, int out_size)
{
    const float* x = (const float*)d_in[0];
    const float* w = (const float*)d_in[1];
    float* out = (float*)d_out;

    prep_w_kernel<<<(NK16 * 2 * 4 * 32 + 255) / 256, 256>>>(w);
    topk_router_mma<<<BSZ / TM, THREADS>>>(x, out);
}